// round 16
// baseline (speedup 1.0000x reference)
#include <cuda_runtime.h>
#include <cuda_fp16.h>
#include <cstdint>

#define D 128
#define PITCH 136              // fp16 elems per smem row = 272 B
#define NT 512

static const int MAX_E = 800000;
static const int MAX_N = 50000;

// g_Q fp16, permuted within each 32-col block: pos = nc + qid*8 + ni*2 + t
// holds column col = nc + ni*8 + qid*2 + t (matches phase-2 accumulator map).
// g_M16: fp16 copy of M (row-major).
__device__ __align__(16) __half g_Q[(size_t)MAX_E * D];    // 204.8 MB
__device__ __align__(16) __half g_M16[(size_t)MAX_E * D];  // 204.8 MB
__device__ float g_h[MAX_E];
__device__ float g_denom[MAX_N];

// ---------------------------------------------------------------------------
__device__ __forceinline__ void mma16816(float c[4], const uint32_t a[4],
                                         const uint32_t b0, const uint32_t b1) {
    asm volatile(
        "mma.sync.aligned.m16n8k16.row.col.f32.f16.f16.f32 "
        "{%0,%1,%2,%3}, {%4,%5,%6,%7}, {%8,%9}, {%0,%1,%2,%3};"
        : "+f"(c[0]), "+f"(c[1]), "+f"(c[2]), "+f"(c[3])
        : "r"(a[0]), "r"(a[1]), "r"(a[2]), "r"(a[3]), "r"(b0), "r"(b1));
}
__device__ __forceinline__ void ldmx4(uint32_t r[4], uint32_t addr) {
    asm volatile("ldmatrix.sync.aligned.m8n8.x4.shared.b16 {%0,%1,%2,%3}, [%4];"
                 : "=r"(r[0]), "=r"(r[1]), "=r"(r[2]), "=r"(r[3]) : "r"(addr));
}
__device__ __forceinline__ void cp16(uint32_t dst_smem, const void* src, int srcBytes) {
    asm volatile("cp.async.cg.shared.global [%0], [%1], 16, %2;"
                 :: "r"(dst_smem), "l"(src), "r"(srcBytes) : "memory");
}
__device__ __forceinline__ void cp_commit() {
    asm volatile("cp.async.commit_group;" ::: "memory");
}
__device__ __forceinline__ void cp_wait0() {
    asm volatile("cp.async.wait_group 0;" ::: "memory");
}

// Phase-1 SMEM layout
static constexpr int S1_RAW = 0;                          // 64 KB raw fp32
static constexpr int S1_A0  = 65536;                      // 128 x 272
static constexpr int S1_A1  = S1_A0 + 128 * 272;
static constexpr int S1_W   = S1_A1 + 128 * 272;          // 128 x 272 (W1)
static constexpr int S1_B   = S1_W + 128 * 272;           // 128 fp32
static constexpr int S1_TOTAL = S1_B + 512;               // 170496

// Phase-2 SMEM layout (tile = 64 rows)
static constexpr int S2_W   = 0;                          // 128 x 272 (W0)
static constexpr int S2_A0  = 34816;                      // 64 x 272 (M16 tile)
static constexpr int S2_A1  = S2_A0 + 64 * 272;           // 52224
static constexpr int S2_Q0  = S2_A1 + 64 * 272;           // 69632
static constexpr int S2_Q1  = S2_Q0 + 64 * 272;           // 87040
static constexpr int S2_S   = S2_Q1 + 64 * 272;           // 104448, 64 fp32
static constexpr int S2_RV0 = S2_S + 256;                 // 64 int
static constexpr int S2_RV1 = S2_RV0 + 256;
static constexpr int S2_DV0 = S2_RV1 + 256;
static constexpr int S2_DV1 = S2_DV0 + 256;
static constexpr int S2_TOTAL = S2_DV1 + 256;             // 105728

// ---------------------------------------------------------------------------
// Phase 1: Q = M @ W1^T + b1 (fp16, permuted) + g_M16 + zero out[]/denom.
// 128-row tiles, 16 warps = 4m(32) x 4n(32). (R13-proven structure, N=128.)
// ---------------------------------------------------------------------------
__global__ __launch_bounds__(NT, 1) void gemm_q(
    const float* __restrict__ M,
    const float* __restrict__ W1, const float* __restrict__ b1,
    float* __restrict__ out, int outN,
    int E, int numTiles)
{
    extern __shared__ char sm[];
    float*  sRaw = (float*)(sm + S1_RAW);
    __half* sW   = (__half*)(sm + S1_W);
    float*  sBias = (float*)(sm + S1_B);
    const uint32_t smBase = (uint32_t)(uint64_t)__cvta_generic_to_shared(sm);
    const uint32_t rawBase = smBase + S1_RAW;

    const int tid  = threadIdx.x;
    const int wid  = tid >> 5;
    const int lane = tid & 31;
    const int gid  = lane >> 2;
    const int qid  = lane & 3;

    // prologue cp.async for first tile
    {
        long row0 = (long)blockIdx.x * 128;
        if (blockIdx.x < numTiles) {
            #pragma unroll
            for (int t = 0; t < 8; t++) {
                int chunk = tid + t * NT;
                int r = chunk >> 5;
                int sz = (row0 + r < (long)E) ? 16 : 0;
                cp16(rawBase + chunk * 16,
                     (const char*)M + (row0 * D + (chunk & 31) * 4 + (long)r * D) * 4, sz);
            }
        }
        cp_commit();
    }

    // zero out[]/g_denom[]
    {
        int gstride = gridDim.x * NT;
        int g0 = blockIdx.x * NT + tid;
        float4 z4 = make_float4(0.f, 0.f, 0.f, 0.f);
        int n4 = outN >> 2;
        for (int i = g0; i < n4; i += gstride) ((float4*)out)[i] = z4;
        for (int i = g0; i < MAX_N; i += gstride) g_denom[i] = 0.0f;
    }

    // convert W1
    for (int i = tid; i < 128 * D; i += NT) {
        int n = i >> 7, k = i & 127;
        sW[n * PITCH + k] = __float2half_rn(W1[i]);
    }
    if (tid < 128) sBias[tid] = b1[tid];

    const int mr = (wid >> 2) * 32;
    const int nc = (wid & 3) * 32;

    const int rr = lane & 7;
    const int j  = lane >> 3;
    const uint32_t aOff = (uint32_t)((mr + ((j & 1) << 3) + rr) * 272 + ((j >> 1) << 4));
    const uint32_t aAddr0 = smBase + S1_A0 + aOff;
    const uint32_t aAddr1 = smBase + S1_A1 + aOff;
    uint32_t bAddr[2];
    #pragma unroll
    for (int nip = 0; nip < 2; nip++)
        bAddr[nip] = smBase + S1_W
                   + (uint32_t)((nc + nip * 16 + ((j >> 1) << 3) + rr) * 272
                                + ((j & 1) << 4));

    __syncthreads();

    int buf = 0;
    for (int tile = blockIdx.x; tile < numTiles; tile += gridDim.x) {
        long row0 = (long)tile * 128;
        int next = tile + gridDim.x;
        __half* sA = (__half*)(sm + (buf ? S1_A1 : S1_A0));
        const uint32_t aBase = buf ? aAddr1 : aAddr0;

        cp_wait0();

        uint2 hv[8];
        #pragma unroll
        for (int t = 0; t < 8; t++) {
            int idx4 = tid + t * NT;
            int r  = idx4 >> 5;
            int c  = (idx4 & 31) * 4;
            float4 v = *(const float4*)(sRaw + r * 128 + c);
            __half2 h01 = __floats2half2_rn(v.x, v.y);
            __half2 h23 = __floats2half2_rn(v.z, v.w);
            hv[t] = make_uint2(*(uint32_t*)&h01, *(uint32_t*)&h23);
            *(uint2*)(sA + r * PITCH + c) = hv[t];
        }
        __syncthreads();

        // g_M16 stores after barrier (drain during compute)
        #pragma unroll
        for (int t = 0; t < 8; t++) {
            int idx4 = tid + t * NT;
            int r  = idx4 >> 5;
            int c  = (idx4 & 31) * 4;
            if (row0 + r < (long)E)
                *(uint2*)(g_M16 + (row0 + r) * D + c) = hv[t];
        }

        if (next < numTiles) {
            long nrow0 = (long)next * 128;
            #pragma unroll
            for (int t = 0; t < 8; t++) {
                int chunk = tid + t * NT;
                int r = chunk >> 5;
                int sz = (nrow0 + r < (long)E) ? 16 : 0;
                cp16(rawBase + chunk * 16,
                     (const char*)M + (nrow0 * D + (chunk & 31) * 4 + (long)r * D) * 4, sz);
            }
        }
        cp_commit();

        float acc[2][4][4];
        #pragma unroll
        for (int mi = 0; mi < 2; mi++)
            #pragma unroll
            for (int ni = 0; ni < 4; ni++)
                #pragma unroll
                for (int r = 0; r < 4; r++) acc[mi][ni][r] = 0.0f;

        #pragma unroll
        for (int ks = 0; ks < 8; ks++) {
            const uint32_t ko = (uint32_t)(ks * 32);
            uint32_t a[2][4];
            ldmx4(a[0], aBase + ko);
            ldmx4(a[1], aBase + 16 * 272 + ko);
            uint32_t b0v[4], b1v[4];
            ldmx4(b0v, bAddr[0] + ko);
            ldmx4(b1v, bAddr[1] + ko);
            #pragma unroll
            for (int mi = 0; mi < 2; mi++) {
                mma16816(acc[mi][0], a[mi], b0v[0], b0v[1]);
                mma16816(acc[mi][1], a[mi], b0v[2], b0v[3]);
                mma16816(acc[mi][2], a[mi], b1v[0], b1v[1]);
                mma16816(acc[mi][3], a[mi], b1v[2], b1v[3]);
            }
        }

        // permuted store: thread's 8 halves contiguous at nc + qid*8
        #pragma unroll
        for (int mi = 0; mi < 2; mi++) {
            long rowA = row0 + mr + mi * 16 + gid;
            long rowB = rowA + 8;
            __half2 hA[4], hB[4];
            #pragma unroll
            for (int ni = 0; ni < 4; ni++) {
                int col = nc + ni * 8 + qid * 2;
                float bx = sBias[col], by = sBias[col + 1];
                hA[ni] = __floats2half2_rn(acc[mi][ni][0] + bx, acc[mi][ni][1] + by);
                hB[ni] = __floats2half2_rn(acc[mi][ni][2] + bx, acc[mi][ni][3] + by);
            }
            if (rowA < (long)E)
                *(uint4*)(g_Q + rowA * D + nc + qid * 8) = make_uint4(
                    *(uint32_t*)&hA[0], *(uint32_t*)&hA[1],
                    *(uint32_t*)&hA[2], *(uint32_t*)&hA[3]);
            if (rowB < (long)E)
                *(uint4*)(g_Q + rowB * D + nc + qid * 8) = make_uint4(
                    *(uint32_t*)&hB[0], *(uint32_t*)&hB[1],
                    *(uint32_t*)&hB[2], *(uint32_t*)&hB[3]);
        }
        buf ^= 1;
    }
}

// ---------------------------------------------------------------------------
// Phase 2: fused P-GEMM + edge pass, 64-row tiles, one-tile-ahead cp.async
// prefetch of BOTH the M16 tile and the gathered Q[rev] rows.
//   P = M16_tile @ W0^T (fp32 accumulators, never materialized)
//   s = a . LReLU(P + b0 + Q[rev]);  h = exp(s + ab)
//   denom[dest] += h;  g_h = h;  out[dest] += h * M16 (from smem)
// ---------------------------------------------------------------------------
__global__ __launch_bounds__(NT, 1) void fused_pe(
    const float* __restrict__ W0, const float* __restrict__ b0,
    const float* __restrict__ a_w, const float* __restrict__ a_b,
    const int* __restrict__ rev, const int* __restrict__ dest,
    float* __restrict__ out, int E, int numTiles)
{
    extern __shared__ char sm[];
    __half* sW = (__half*)(sm + S2_W);
    float*  sS = (float*)(sm + S2_S);
    const uint32_t smBase = (uint32_t)(uint64_t)__cvta_generic_to_shared(sm);

    const int tid  = threadIdx.x;
    const int wid  = tid >> 5;
    const int lane = tid & 31;
    const int gid  = lane >> 2;
    const int qid  = lane & 3;

    // convert W0
    for (int i = tid; i < 128 * D; i += NT) {
        int n = i >> 7, k = i & 127;
        sW[n * PITCH + k] = __float2half_rn(W0[i]);
    }

    const int mr = (wid >> 2) * 16;      // 0|16|32|48
    const int nc = (wid & 3) * 32;       // 0|32|64|96

    // loop-invariant a_w / b0 at this thread's accumulator columns
    float aw[8], bw[8];
    #pragma unroll
    for (int ni = 0; ni < 4; ni++)
        #pragma unroll
        for (int t = 0; t < 2; t++) {
            int col = nc + ni * 8 + qid * 2 + t;
            aw[ni * 2 + t] = a_w[col];
            bw[ni * 2 + t] = b0[col];
        }
    const float ab = a_b[0];

    const int rr = lane & 7;
    const int j  = lane >> 3;
    const uint32_t aOff = (uint32_t)((mr + ((j & 1) << 3) + rr) * 272 + ((j >> 1) << 4));
    const uint32_t aAddr0 = smBase + S2_A0 + aOff;
    const uint32_t aAddr1 = smBase + S2_A1 + aOff;
    uint32_t bAddr0 = smBase + S2_W
        + (uint32_t)((nc + ((j >> 1) << 3) + rr) * 272 + ((j & 1) << 4));
    uint32_t bAddr1 = smBase + S2_W
        + (uint32_t)((nc + 16 + ((j >> 1) << 3) + rr) * 272 + ((j & 1) << 4));

    // --- index staging: sIDX[0] <- tile0; regs <- tile1 (two-ahead scheme)
    int rvN = 0, dvN = 0;
    if (tid < 64) {
        long r0 = (long)blockIdx.x * 64 + tid;
        int v_rv = (r0 < (long)E) ? rev[r0] : 0;
        int v_dv = (r0 < (long)E) ? dest[r0] : 0;
        ((int*)(sm + S2_RV0))[tid] = v_rv;
        ((int*)(sm + S2_DV0))[tid] = v_dv;
        long t1 = (long)blockIdx.x + gridDim.x;
        long r1 = t1 * 64 + tid;
        if (t1 < (long)numTiles && r1 < (long)E) { rvN = rev[r1]; dvN = dest[r1]; }
    }
    __syncthreads();

    // --- prologue cp.async: tile0 -> buf0 (M16 tile + gathered Q rows)
    if (blockIdx.x < numTiles) {
        const int* srv = (const int*)(sm + S2_RV0);
        #pragma unroll
        for (int c = 0; c < 2; c++) {
            int idx = tid + c * NT;           // 0..1023
            int row = idx >> 4, ch = idx & 15;
            long grow = (long)blockIdx.x * 64 + row;
            int szM = (grow < (long)E) ? 16 : 0;
            cp16(smBase + S2_A0 + row * 272 + ch * 16,
                 (const char*)g_M16 + grow * 256 + ch * 16, szM);
            long qrow = srv[row];
            cp16(smBase + S2_Q0 + row * 272 + ch * 16,
                 (const char*)g_Q + qrow * 256 + ch * 16, 16);
        }
    }
    cp_commit();

    int k = 0;
    for (int tile = blockIdx.x; tile < numTiles; tile += gridDim.x, k++) {
        const int b = k & 1;
        long row0 = (long)tile * 64;

        cp_wait0();
        __syncthreads();       // B1: A16[b]/Q[b] ready; prev iter fully done

        // stage indices for tile+1 into buffers b^1; prefetch tile+2 indices
        if (tid < 64) {
            sS[tid] = 0.0f;
            ((int*)(sm + (b ? S2_RV0 : S2_RV1)))[tid] = rvN;
            ((int*)(sm + (b ? S2_DV0 : S2_DV1)))[tid] = dvN;
            long t2 = (long)tile + 2L * gridDim.x;
            long r2 = t2 * 64 + tid;
            rvN = dvN = 0;
            if (t2 < (long)numTiles && r2 < (long)E) { rvN = rev[r2]; dvN = dest[r2]; }
        }
        __syncthreads();       // B2: sIDX[b^1], sS visible

        // issue cp.async for tile+1 into buffers b^1
        int tn = tile + gridDim.x;
        if (tn < numTiles) {
            const int* srvN = (const int*)(sm + (b ? S2_RV0 : S2_RV1));
            uint32_t a16n = smBase + (b ? S2_A0 : S2_A1);
            uint32_t qn   = smBase + (b ? S2_Q0 : S2_Q1);
            #pragma unroll
            for (int c = 0; c < 2; c++) {
                int idx = tid + c * NT;
                int row = idx >> 4, ch = idx & 15;
                long grow = (long)tn * 64 + row;
                int szM = (grow < (long)E) ? 16 : 0;
                cp16(a16n + row * 272 + ch * 16,
                     (const char*)g_M16 + grow * 256 + ch * 16, szM);
                long qrow = srvN[row];
                cp16(qn + row * 272 + ch * 16,
                     (const char*)g_Q + qrow * 256 + ch * 16, 16);
            }
        }
        cp_commit();

        // --- MMA: P warp tile 16x32 in accumulators
        const uint32_t aBase = b ? aAddr1 : aAddr0;
        float acc[4][4];
        #pragma unroll
        for (int ni = 0; ni < 4; ni++)
            #pragma unroll
            for (int r = 0; r < 4; r++) acc[ni][r] = 0.0f;

        #pragma unroll
        for (int ks = 0; ks < 8; ks++) {
            const uint32_t ko = (uint32_t)(ks * 32);
            uint32_t a[4];
            ldmx4(a, aBase + ko);
            uint32_t b0v[4], b1v[4];
            ldmx4(b0v, bAddr0 + ko);
            ldmx4(b1v, bAddr1 + ko);
            mma16816(acc[0], a, b0v[0], b0v[1]);
            mma16816(acc[1], a, b0v[2], b0v[3]);
            mma16816(acc[2], a, b1v[0], b1v[1]);
            mma16816(acc[3], a, b1v[2], b1v[3]);
        }

        // --- score partials: z = LReLU(P + b0 + Q), dot a_w
        {
            const char* qb = sm + (b ? S2_Q1 : S2_Q0);
            int rlA = mr + gid;
            int rlB = rlA + 8;
            float pA = 0.f, pB = 0.f;
            #pragma unroll
            for (int ni = 0; ni < 4; ni++) {
                int qoff = (nc + qid * 8 + ni * 2) * 2;
                float2 fa = __half22float2(*(const __half2*)(qb + rlA * 272 + qoff));
                float2 fb = __half22float2(*(const __half2*)(qb + rlB * 272 + qoff));
                float z0 = acc[ni][0] + bw[ni*2]   + fa.x; z0 = z0 > 0.f ? z0 : 0.2f * z0;
                float z1 = acc[ni][1] + bw[ni*2+1] + fa.y; z1 = z1 > 0.f ? z1 : 0.2f * z1;
                float z2 = acc[ni][2] + bw[ni*2]   + fb.x; z2 = z2 > 0.f ? z2 : 0.2f * z2;
                float z3 = acc[ni][3] + bw[ni*2+1] + fb.y; z3 = z3 > 0.f ? z3 : 0.2f * z3;
                pA += aw[ni*2] * z0 + aw[ni*2+1] * z1;
                pB += aw[ni*2] * z2 + aw[ni*2+1] * z3;
            }
            pA += __shfl_xor_sync(0xffffffffu, pA, 1);
            pA += __shfl_xor_sync(0xffffffffu, pA, 2);
            pB += __shfl_xor_sync(0xffffffffu, pB, 1);
            pB += __shfl_xor_sync(0xffffffffu, pB, 2);
            if (qid == 0) {
                atomicAdd(&sS[rlA], pA);
                atomicAdd(&sS[rlB], pB);
            }
        }
        __syncthreads();       // B3: scores final

        // --- h, denom, scatter (warp wid owns rows wid*4..wid*4+3)
        {
            const char* a16 = sm + (b ? S2_A1 : S2_A0);
            const int* sdv = (const int*)(sm + (b ? S2_DV1 : S2_DV0));
            #pragma unroll
            for (int i = 0; i < 4; i++) {
                int rl = (wid << 2) + i;
                long grow = row0 + rl;
                if (grow >= (long)E) continue;
                float h = expf(sS[rl] + ab);
                int d = sdv[rl];
                if (lane == i) {
                    g_h[grow] = h;
                    atomicAdd(&g_denom[d], h);
                }
                uint2 mh = *(const uint2*)(a16 + rl * 272 + lane * 8);
                float2 m01 = __half22float2(*(const __half2*)&mh.x);
                float2 m23 = __half22float2(*(const __half2*)&mh.y);
                float* o = out + (long)d * D + lane * 4;
                asm volatile("red.global.add.v4.f32 [%0], {%1, %2, %3, %4};"
                             :: "l"(o), "f"(h * m01.x), "f"(h * m01.y),
                                "f"(h * m23.x), "f"(h * m23.y)
                             : "memory");
            }
        }
        // next iter's cp_wait0 + B1 protect buffer reuse
    }
    cp_wait0();   // drain any outstanding prefetch before exit
}

// ---------------------------------------------------------------------------
// K3: normalize out rows by denom and compute alpha = h / denom[dest].
// ---------------------------------------------------------------------------
__global__ __launch_bounds__(256) void normalize_kernel(
    const int* __restrict__ dest,
    float* __restrict__ out, float* __restrict__ alpha_out, int N, int E)
{
    int i = blockIdx.x * blockDim.x + threadIdx.x;
    int nOut = N * 32;
    if (i < nOut) {
        int n = i >> 5;
        float inv = 1.0f / g_denom[n];
        float4* p = (float4*)out + i;
        float4 v = *p;
        v.x *= inv; v.y *= inv; v.z *= inv; v.w *= inv;
        *p = v;
    } else if (i < nOut + E) {
        int e = i - nOut;
        alpha_out[e] = g_h[e] / g_denom[dest[e]];
    }
}

// ---------------------------------------------------------------------------
extern "C" void kernel_launch(void* const* d_in, const int* in_sizes, int n_in,
                              void* d_out, int out_size)
{
    const float* M    = (const float*)d_in[0];
    const int*   dest = (const int*)d_in[1];
    const int*   rev  = (const int*)d_in[2];
    int base = (n_in >= 10) ? 4 : 3;
    const float* W0   = (const float*)d_in[base + 0];
    const float* b0   = (const float*)d_in[base + 1];
    const float* W1   = (const float*)d_in[base + 2];
    const float* b1   = (const float*)d_in[base + 3];
    const float* a_w  = (const float*)d_in[base + 4];
    const float* a_b  = (const float*)d_in[base + 5];

    int E = in_sizes[1];
    int N = (out_size - E) / D;

    float* out   = (float*)d_out;
    float* alpha = (float*)d_out + (long)N * D;

    cudaFuncSetAttribute(gemm_q,
        cudaFuncAttributeMaxDynamicSharedMemorySize, S1_TOTAL);
    cudaFuncSetAttribute(fused_pe,
        cudaFuncAttributeMaxDynamicSharedMemorySize, S2_TOTAL);

    // Phase 1: Q GEMM + M16 (zeroes out[]/denom)
    int numTilesQ = (E + 127) / 128;
    gemm_q<<<148, NT, S1_TOTAL>>>(M, W1, b1, out, N * D, E, numTilesQ);

    // Phase 2: fused P GEMM + edge pass (prefetched gather)
    int numTilesP = (E + 63) / 64;
    fused_pe<<<148, NT, S2_TOTAL>>>(W0, b0, a_w, a_b, rev, dest,
                                    out, E, numTilesP);

    // K3: normalize + alpha
    int totWork = N * 32 + E;
    normalize_kernel<<<(totWork + 255) / 256, 256>>>(dest, out, alpha, N, E);
}

// round 17
// speedup vs baseline: 1.0693x; 1.0693x over previous
#include <cuda_runtime.h>
#include <cuda_fp16.h>
#include <cstdint>

#define D 128
#define PITCH 136              // fp16 elems per smem row = 272 B
#define NT 512

static const int MAX_E = 800000;
static const int MAX_N = 50000;

// g_Q fp16, permuted within each 32-col block: pos = nc + qid*8 + ni*2 + t
// holds column col = nc + ni*8 + qid*2 + t (matches phase-2 accumulator map).
// g_M16: fp16 copy of M (row-major).
__device__ __align__(16) __half g_Q[(size_t)MAX_E * D];    // 204.8 MB
__device__ __align__(16) __half g_M16[(size_t)MAX_E * D];  // 204.8 MB
__device__ float g_h[MAX_E];
__device__ float g_denom[MAX_N];

// ---------------------------------------------------------------------------
__device__ __forceinline__ void mma16816(float c[4], const uint32_t a[4],
                                         const uint32_t b0, const uint32_t b1) {
    asm volatile(
        "mma.sync.aligned.m16n8k16.row.col.f32.f16.f16.f32 "
        "{%0,%1,%2,%3}, {%4,%5,%6,%7}, {%8,%9}, {%0,%1,%2,%3};"
        : "+f"(c[0]), "+f"(c[1]), "+f"(c[2]), "+f"(c[3])
        : "r"(a[0]), "r"(a[1]), "r"(a[2]), "r"(a[3]), "r"(b0), "r"(b1));
}
__device__ __forceinline__ void ldmx4(uint32_t r[4], uint32_t addr) {
    asm volatile("ldmatrix.sync.aligned.m8n8.x4.shared.b16 {%0,%1,%2,%3}, [%4];"
                 : "=r"(r[0]), "=r"(r[1]), "=r"(r[2]), "=r"(r[3]) : "r"(addr));
}
__device__ __forceinline__ void cp16(uint32_t dst_smem, const void* src, int srcBytes) {
    asm volatile("cp.async.cg.shared.global [%0], [%1], 16, %2;"
                 :: "r"(dst_smem), "l"(src), "r"(srcBytes) : "memory");
}
__device__ __forceinline__ void cp_commit() {
    asm volatile("cp.async.commit_group;" ::: "memory");
}
__device__ __forceinline__ void cp_wait0() {
    asm volatile("cp.async.wait_group 0;" ::: "memory");
}

// Phase-1 SMEM layout
static constexpr int S1_RAW = 0;                          // 64 KB raw fp32
static constexpr int S1_A0  = 65536;                      // 128 x 272
static constexpr int S1_A1  = S1_A0 + 128 * 272;
static constexpr int S1_W   = S1_A1 + 128 * 272;          // 128 x 272 (W1)
static constexpr int S1_B   = S1_W + 128 * 272;           // 128 fp32
static constexpr int S1_TOTAL = S1_B + 512;               // 170496

// Phase-2 SMEM layout (tile = 128 rows, double-buffered M16 + Q)
static constexpr int S2_W   = 0;                          // 128 x 272 (W0)
static constexpr int S2_A0  = 34816;                      // 128 x 272
static constexpr int S2_A1  = S2_A0 + 128 * 272;          // 69632
static constexpr int S2_Q0  = S2_A1 + 128 * 272;          // 104448
static constexpr int S2_Q1  = S2_Q0 + 128 * 272;          // 139264
static constexpr int S2_S   = S2_Q1 + 128 * 272;          // 174080, 128 fp32
static constexpr int S2_RV0 = S2_S + 512;                 // 128 int
static constexpr int S2_RV1 = S2_RV0 + 512;
static constexpr int S2_DV0 = S2_RV1 + 512;
static constexpr int S2_DV1 = S2_DV0 + 512;
static constexpr int S2_TOTAL = S2_DV1 + 512;             // 176640

// ---------------------------------------------------------------------------
// Phase 1: Q = M @ W1^T + b1 (fp16, permuted) + g_M16 + zero out[]/denom.
// 128-row tiles, 16 warps = 4m(32) x 4n(32).
// ---------------------------------------------------------------------------
__global__ __launch_bounds__(NT, 1) void gemm_q(
    const float* __restrict__ M,
    const float* __restrict__ W1, const float* __restrict__ b1,
    float* __restrict__ out, int outN,
    int E, int numTiles)
{
    extern __shared__ char sm[];
    float*  sRaw = (float*)(sm + S1_RAW);
    __half* sW   = (__half*)(sm + S1_W);
    float*  sBias = (float*)(sm + S1_B);
    const uint32_t smBase = (uint32_t)(uint64_t)__cvta_generic_to_shared(sm);
    const uint32_t rawBase = smBase + S1_RAW;

    const int tid  = threadIdx.x;
    const int wid  = tid >> 5;
    const int lane = tid & 31;
    const int gid  = lane >> 2;
    const int qid  = lane & 3;

    // prologue cp.async for first tile
    {
        long row0 = (long)blockIdx.x * 128;
        if (blockIdx.x < numTiles) {
            #pragma unroll
            for (int t = 0; t < 8; t++) {
                int chunk = tid + t * NT;
                int r = chunk >> 5;
                int sz = (row0 + r < (long)E) ? 16 : 0;
                cp16(rawBase + chunk * 16,
                     (const char*)M + (row0 * D + (chunk & 31) * 4 + (long)r * D) * 4, sz);
            }
        }
        cp_commit();
    }

    // zero out[]/g_denom[]
    {
        int gstride = gridDim.x * NT;
        int g0 = blockIdx.x * NT + tid;
        float4 z4 = make_float4(0.f, 0.f, 0.f, 0.f);
        int n4 = outN >> 2;
        for (int i = g0; i < n4; i += gstride) ((float4*)out)[i] = z4;
        for (int i = g0; i < MAX_N; i += gstride) g_denom[i] = 0.0f;
    }

    // convert W1
    for (int i = tid; i < 128 * D; i += NT) {
        int n = i >> 7, k = i & 127;
        sW[n * PITCH + k] = __float2half_rn(W1[i]);
    }
    if (tid < 128) sBias[tid] = b1[tid];

    const int mr = (wid >> 2) * 32;
    const int nc = (wid & 3) * 32;

    const int rr = lane & 7;
    const int j  = lane >> 3;
    const uint32_t aOff = (uint32_t)((mr + ((j & 1) << 3) + rr) * 272 + ((j >> 1) << 4));
    const uint32_t aAddr0 = smBase + S1_A0 + aOff;
    const uint32_t aAddr1 = smBase + S1_A1 + aOff;
    uint32_t bAddr[2];
    #pragma unroll
    for (int nip = 0; nip < 2; nip++)
        bAddr[nip] = smBase + S1_W
                   + (uint32_t)((nc + nip * 16 + ((j >> 1) << 3) + rr) * 272
                                + ((j & 1) << 4));

    __syncthreads();

    int buf = 0;
    for (int tile = blockIdx.x; tile < numTiles; tile += gridDim.x) {
        long row0 = (long)tile * 128;
        int next = tile + gridDim.x;
        __half* sA = (__half*)(sm + (buf ? S1_A1 : S1_A0));
        const uint32_t aBase = buf ? aAddr1 : aAddr0;

        cp_wait0();

        uint2 hv[8];
        #pragma unroll
        for (int t = 0; t < 8; t++) {
            int idx4 = tid + t * NT;
            int r  = idx4 >> 5;
            int c  = (idx4 & 31) * 4;
            float4 v = *(const float4*)(sRaw + r * 128 + c);
            __half2 h01 = __floats2half2_rn(v.x, v.y);
            __half2 h23 = __floats2half2_rn(v.z, v.w);
            hv[t] = make_uint2(*(uint32_t*)&h01, *(uint32_t*)&h23);
            *(uint2*)(sA + r * PITCH + c) = hv[t];
        }
        __syncthreads();

        // g_M16 stores after barrier (drain during compute)
        #pragma unroll
        for (int t = 0; t < 8; t++) {
            int idx4 = tid + t * NT;
            int r  = idx4 >> 5;
            int c  = (idx4 & 31) * 4;
            if (row0 + r < (long)E)
                *(uint2*)(g_M16 + (row0 + r) * D + c) = hv[t];
        }

        if (next < numTiles) {
            long nrow0 = (long)next * 128;
            #pragma unroll
            for (int t = 0; t < 8; t++) {
                int chunk = tid + t * NT;
                int r = chunk >> 5;
                int sz = (nrow0 + r < (long)E) ? 16 : 0;
                cp16(rawBase + chunk * 16,
                     (const char*)M + (nrow0 * D + (chunk & 31) * 4 + (long)r * D) * 4, sz);
            }
        }
        cp_commit();

        float acc[2][4][4];
        #pragma unroll
        for (int mi = 0; mi < 2; mi++)
            #pragma unroll
            for (int ni = 0; ni < 4; ni++)
                #pragma unroll
                for (int r = 0; r < 4; r++) acc[mi][ni][r] = 0.0f;

        #pragma unroll
        for (int ks = 0; ks < 8; ks++) {
            const uint32_t ko = (uint32_t)(ks * 32);
            uint32_t a[2][4];
            ldmx4(a[0], aBase + ko);
            ldmx4(a[1], aBase + 16 * 272 + ko);
            uint32_t b0v[4], b1v[4];
            ldmx4(b0v, bAddr[0] + ko);
            ldmx4(b1v, bAddr[1] + ko);
            #pragma unroll
            for (int mi = 0; mi < 2; mi++) {
                mma16816(acc[mi][0], a[mi], b0v[0], b0v[1]);
                mma16816(acc[mi][1], a[mi], b0v[2], b0v[3]);
                mma16816(acc[mi][2], a[mi], b1v[0], b1v[1]);
                mma16816(acc[mi][3], a[mi], b1v[2], b1v[3]);
            }
        }

        // permuted store: thread's 8 halves contiguous at nc + qid*8
        #pragma unroll
        for (int mi = 0; mi < 2; mi++) {
            long rowA = row0 + mr + mi * 16 + gid;
            long rowB = rowA + 8;
            __half2 hA[4], hB[4];
            #pragma unroll
            for (int ni = 0; ni < 4; ni++) {
                int col = nc + ni * 8 + qid * 2;
                float bx = sBias[col], by = sBias[col + 1];
                hA[ni] = __floats2half2_rn(acc[mi][ni][0] + bx, acc[mi][ni][1] + by);
                hB[ni] = __floats2half2_rn(acc[mi][ni][2] + bx, acc[mi][ni][3] + by);
            }
            if (rowA < (long)E)
                *(uint4*)(g_Q + rowA * D + nc + qid * 8) = make_uint4(
                    *(uint32_t*)&hA[0], *(uint32_t*)&hA[1],
                    *(uint32_t*)&hA[2], *(uint32_t*)&hA[3]);
            if (rowB < (long)E)
                *(uint4*)(g_Q + rowB * D + nc + qid * 8) = make_uint4(
                    *(uint32_t*)&hB[0], *(uint32_t*)&hB[1],
                    *(uint32_t*)&hB[2], *(uint32_t*)&hB[3]);
        }
        buf ^= 1;
    }
}

// ---------------------------------------------------------------------------
// Phase 2: fused P-GEMM + edge pass, 128-row tiles, one-tile-ahead cp.async
// prefetch of BOTH the M16 tile and the gathered Q[rev] rows.
//   P = M16_tile @ W0^T (fp32 accumulators, never materialized)
//   s = a . LReLU(P + b0 + Q[rev]);  h = exp(s + ab)
//   denom[dest] += h;  g_h = h;  out[dest] += h * M16 (from smem)
// ---------------------------------------------------------------------------
__global__ __launch_bounds__(NT, 1) void fused_pe(
    const float* __restrict__ W0, const float* __restrict__ b0,
    const float* __restrict__ a_w, const float* __restrict__ a_b,
    const int* __restrict__ rev, const int* __restrict__ dest,
    float* __restrict__ out, int E, int numTiles)
{
    extern __shared__ char sm[];
    __half* sW = (__half*)(sm + S2_W);
    float*  sS = (float*)(sm + S2_S);
    const uint32_t smBase = (uint32_t)(uint64_t)__cvta_generic_to_shared(sm);

    const int tid  = threadIdx.x;
    const int wid  = tid >> 5;
    const int lane = tid & 31;
    const int gid  = lane >> 2;
    const int qid  = lane & 3;

    // convert W0
    for (int i = tid; i < 128 * D; i += NT) {
        int n = i >> 7, k = i & 127;
        sW[n * PITCH + k] = __float2half_rn(W0[i]);
    }

    const int mr = (wid >> 2) * 32;      // 0|32|64|96
    const int nc = (wid & 3) * 32;       // 0|32|64|96

    // loop-invariant a_w / b0 at this thread's accumulator columns
    float aw[8], bw[8];
    #pragma unroll
    for (int ni = 0; ni < 4; ni++)
        #pragma unroll
        for (int t = 0; t < 2; t++) {
            int col = nc + ni * 8 + qid * 2 + t;
            aw[ni * 2 + t] = a_w[col];
            bw[ni * 2 + t] = b0[col];
        }
    const float ab = a_b[0];

    const int rr = lane & 7;
    const int j  = lane >> 3;
    const uint32_t aOff = (uint32_t)((mr + ((j & 1) << 3) + rr) * 272 + ((j >> 1) << 4));
    const uint32_t aAddr0 = smBase + S2_A0 + aOff;
    const uint32_t aAddr1 = smBase + S2_A1 + aOff;
    uint32_t bAddr0 = smBase + S2_W
        + (uint32_t)((nc + ((j >> 1) << 3) + rr) * 272 + ((j & 1) << 4));
    uint32_t bAddr1 = smBase + S2_W
        + (uint32_t)((nc + 16 + ((j >> 1) << 3) + rr) * 272 + ((j & 1) << 4));

    // --- index staging: sIDX[0] <- tile0; regs <- tile1
    int rvN = 0, dvN = 0;
    if (tid < 128) {
        long r0 = (long)blockIdx.x * 128 + tid;
        int v_rv = (r0 < (long)E) ? rev[r0] : 0;
        int v_dv = (r0 < (long)E) ? dest[r0] : 0;
        ((int*)(sm + S2_RV0))[tid] = v_rv;
        ((int*)(sm + S2_DV0))[tid] = v_dv;
        long t1 = (long)blockIdx.x + gridDim.x;
        long r1 = t1 * 128 + tid;
        if (t1 < (long)numTiles && r1 < (long)E) { rvN = rev[r1]; dvN = dest[r1]; }
    }
    __syncthreads();

    // --- prologue cp.async: tile0 -> buf0 (M16 tile + gathered Q rows)
    if (blockIdx.x < numTiles) {
        const int* srv = (const int*)(sm + S2_RV0);
        #pragma unroll
        for (int c = 0; c < 4; c++) {
            int idx = tid + c * NT;           // 0..2047
            int row = idx >> 4, ch = idx & 15;
            long grow = (long)blockIdx.x * 128 + row;
            int szM = (grow < (long)E) ? 16 : 0;
            cp16(smBase + S2_A0 + row * 272 + ch * 16,
                 (const char*)g_M16 + grow * 256 + ch * 16, szM);
            long qrow = srv[row];
            cp16(smBase + S2_Q0 + row * 272 + ch * 16,
                 (const char*)g_Q + qrow * 256 + ch * 16, 16);
        }
    }
    cp_commit();

    int k = 0;
    for (int tile = blockIdx.x; tile < numTiles; tile += gridDim.x, k++) {
        const int b = k & 1;
        long row0 = (long)tile * 128;

        cp_wait0();
        __syncthreads();       // B1: A16[b]/Q[b] ready; prev iter fully done

        // stage indices for tile+1 into slot b^1; prefetch tile+2 indices
        if (tid < 128) {
            sS[tid] = 0.0f;
            ((int*)(sm + (b ? S2_RV0 : S2_RV1)))[tid] = rvN;
            ((int*)(sm + (b ? S2_DV0 : S2_DV1)))[tid] = dvN;
            long t2 = (long)tile + 2L * gridDim.x;
            long r2 = t2 * 128 + tid;
            rvN = dvN = 0;
            if (t2 < (long)numTiles && r2 < (long)E) { rvN = rev[r2]; dvN = dest[r2]; }
        }
        __syncthreads();       // B2: sIDX[b^1], sS visible

        // issue cp.async for tile+1 into buffers b^1
        int tn = tile + gridDim.x;
        if (tn < numTiles) {
            const int* srvN = (const int*)(sm + (b ? S2_RV0 : S2_RV1));
            uint32_t a16n = smBase + (b ? S2_A0 : S2_A1);
            uint32_t qn   = smBase + (b ? S2_Q0 : S2_Q1);
            #pragma unroll
            for (int c = 0; c < 4; c++) {
                int idx = tid + c * NT;
                int row = idx >> 4, ch = idx & 15;
                long grow = (long)tn * 128 + row;
                int szM = (grow < (long)E) ? 16 : 0;
                cp16(a16n + row * 272 + ch * 16,
                     (const char*)g_M16 + grow * 256 + ch * 16, szM);
                long qrow = srvN[row];
                cp16(qn + row * 272 + ch * 16,
                     (const char*)g_Q + qrow * 256 + ch * 16, 16);
            }
        }
        cp_commit();

        // --- MMA: P warp tile 32x32 in accumulators
        const uint32_t aBase = b ? aAddr1 : aAddr0;
        float acc[2][4][4];
        #pragma unroll
        for (int mi = 0; mi < 2; mi++)
            #pragma unroll
            for (int ni = 0; ni < 4; ni++)
                #pragma unroll
                for (int r = 0; r < 4; r++) acc[mi][ni][r] = 0.0f;

        #pragma unroll
        for (int ks = 0; ks < 8; ks++) {
            const uint32_t ko = (uint32_t)(ks * 32);
            uint32_t a[2][4];
            ldmx4(a[0], aBase + ko);
            ldmx4(a[1], aBase + 16 * 272 + ko);
            uint32_t b0v[4], b1v[4];
            ldmx4(b0v, bAddr0 + ko);
            ldmx4(b1v, bAddr1 + ko);
            #pragma unroll
            for (int mi = 0; mi < 2; mi++) {
                mma16816(acc[mi][0], a[mi], b0v[0], b0v[1]);
                mma16816(acc[mi][1], a[mi], b0v[2], b0v[3]);
                mma16816(acc[mi][2], a[mi], b1v[0], b1v[1]);
                mma16816(acc[mi][3], a[mi], b1v[2], b1v[3]);
            }
        }

        // --- score partials: z = LReLU(P + b0 + Q), dot a_w
        {
            const char* qb = sm + (b ? S2_Q1 : S2_Q0);
            #pragma unroll
            for (int mi = 0; mi < 2; mi++) {
                int rlA = mr + mi * 16 + gid;
                int rlB = rlA + 8;
                float pA = 0.f, pB = 0.f;
                #pragma unroll
                for (int ni = 0; ni < 4; ni++) {
                    int qoff = (nc + qid * 8 + ni * 2) * 2;
                    float2 fa = __half22float2(*(const __half2*)(qb + rlA * 272 + qoff));
                    float2 fb = __half22float2(*(const __half2*)(qb + rlB * 272 + qoff));
                    float z0 = acc[mi][ni][0] + bw[ni*2]   + fa.x; z0 = z0 > 0.f ? z0 : 0.2f * z0;
                    float z1 = acc[mi][ni][1] + bw[ni*2+1] + fa.y; z1 = z1 > 0.f ? z1 : 0.2f * z1;
                    float z2 = acc[mi][ni][2] + bw[ni*2]   + fb.x; z2 = z2 > 0.f ? z2 : 0.2f * z2;
                    float z3 = acc[mi][ni][3] + bw[ni*2+1] + fb.y; z3 = z3 > 0.f ? z3 : 0.2f * z3;
                    pA += aw[ni*2] * z0 + aw[ni*2+1] * z1;
                    pB += aw[ni*2] * z2 + aw[ni*2+1] * z3;
                }
                pA += __shfl_xor_sync(0xffffffffu, pA, 1);
                pA += __shfl_xor_sync(0xffffffffu, pA, 2);
                pB += __shfl_xor_sync(0xffffffffu, pB, 1);
                pB += __shfl_xor_sync(0xffffffffu, pB, 2);
                if (qid == 0) {
                    atomicAdd(&sS[rlA], pA);
                    atomicAdd(&sS[rlB], pB);
                }
            }
        }
        __syncthreads();       // B3: scores final

        // --- h, denom, scatter (warp wid owns rows wid*8..wid*8+7)
        {
            const char* a16 = sm + (b ? S2_A1 : S2_A0);
            const int* sdv = (const int*)(sm + (b ? S2_DV1 : S2_DV0));
            #pragma unroll
            for (int i = 0; i < 8; i++) {
                int rl = (wid << 3) + i;
                long grow = row0 + rl;
                if (grow >= (long)E) continue;
                float h = expf(sS[rl] + ab);
                int d = sdv[rl];
                if (lane == i) {
                    g_h[grow] = h;
                    atomicAdd(&g_denom[d], h);
                }
                uint2 mh = *(const uint2*)(a16 + rl * 272 + lane * 8);
                float2 m01 = __half22float2(*(const __half2*)&mh.x);
                float2 m23 = __half22float2(*(const __half2*)&mh.y);
                float* o = out + (long)d * D + lane * 4;
                asm volatile("red.global.add.v4.f32 [%0], {%1, %2, %3, %4};"
                             :: "l"(o), "f"(h * m01.x), "f"(h * m01.y),
                                "f"(h * m23.x), "f"(h * m23.y)
                             : "memory");
            }
        }
        // next iter's cp_wait0 + B1 protect buffer reuse
    }
    cp_wait0();   // drain outstanding prefetch before exit
}

// ---------------------------------------------------------------------------
// K3: normalize out rows by denom and compute alpha = h / denom[dest].
// ---------------------------------------------------------------------------
__global__ __launch_bounds__(256) void normalize_kernel(
    const int* __restrict__ dest,
    float* __restrict__ out, float* __restrict__ alpha_out, int N, int E)
{
    int i = blockIdx.x * blockDim.x + threadIdx.x;
    int nOut = N * 32;
    if (i < nOut) {
        int n = i >> 5;
        float inv = 1.0f / g_denom[n];
        float4* p = (float4*)out + i;
        float4 v = *p;
        v.x *= inv; v.y *= inv; v.z *= inv; v.w *= inv;
        *p = v;
    } else if (i < nOut + E) {
        int e = i - nOut;
        alpha_out[e] = g_h[e] / g_denom[dest[e]];
    }
}

// ---------------------------------------------------------------------------
extern "C" void kernel_launch(void* const* d_in, const int* in_sizes, int n_in,
                              void* d_out, int out_size)
{
    const float* M    = (const float*)d_in[0];
    const int*   dest = (const int*)d_in[1];
    const int*   rev  = (const int*)d_in[2];
    int base = (n_in >= 10) ? 4 : 3;
    const float* W0   = (const float*)d_in[base + 0];
    const float* b0   = (const float*)d_in[base + 1];
    const float* W1   = (const float*)d_in[base + 2];
    const float* b1   = (const float*)d_in[base + 3];
    const float* a_w  = (const float*)d_in[base + 4];
    const float* a_b  = (const float*)d_in[base + 5];

    int E = in_sizes[1];
    int N = (out_size - E) / D;

    float* out   = (float*)d_out;
    float* alpha = (float*)d_out + (long)N * D;

    cudaFuncSetAttribute(gemm_q,
        cudaFuncAttributeMaxDynamicSharedMemorySize, S1_TOTAL);
    cudaFuncSetAttribute(fused_pe,
        cudaFuncAttributeMaxDynamicSharedMemorySize, S2_TOTAL);

    // Phase 1: Q GEMM + M16 (zeroes out[]/denom)
    int numTilesQ = (E + 127) / 128;
    gemm_q<<<148, NT, S1_TOTAL>>>(M, W1, b1, out, N * D, E, numTilesQ);

    // Phase 2: fused P GEMM + edge pass (prefetched gather, 128-row tiles)
    int numTilesP = (E + 127) / 128;
    fused_pe<<<148, NT, S2_TOTAL>>>(W0, b0, a_w, a_b, rev, dest,
                                    out, E, numTilesP);

    // K3: normalize + alpha
    int totWork = N * 32 + E;
    normalize_kernel<<<(totWork + 255) / 256, 256>>>(dest, out, alpha, N, E);
}